// round 7
// baseline (speedup 1.0000x reference)
#include <cuda_runtime.h>
#include <cuda_bf16.h>

// diag-embed: out[i, j, k] = (j == k) ? x[i, j] : 0
// x: [8192, 176] fp32, out: [8192, 176, 176] fp32 (~1.015 GB of stores).
//
// R7: R4 body frozen (branchless selects, one L2-hot LDG, __stcs, 1184x256).
// New: contiguous-slab partitioning. Each block owns one contiguous ~857KB
// slab and streams sequentially through it (thread-stride 256, unroll 8),
// instead of R4's whole-grid interleave whose consecutive per-block bursts
// jumped 4.85MB apart. Goal: DRAM row-buffer locality -> recover the ~24%
// idle DRAM cycles.

#define D_MODEL 176u
#define CPR 44u            // float4 chunks per output row
#define BLOCKS 1184u       // 148 SMs * 8 blocks, perfectly balanced
#define THREADS 256u

__global__ __launch_bounds__(THREADS) void diag_embed_kernel(
        const float* __restrict__ x,
        float4* __restrict__ out,
        unsigned n4, unsigned span) {
    // This block's contiguous slab: [start, end)
    const unsigned start = blockIdx.x * span;
    unsigned end = start + span;
    if (end > n4) end = n4;

    unsigned g = start + threadIdx.x;

    #pragma unroll 8
    for (; g < end; g += THREADS) {
        unsigned rowg = g / CPR;                 // 32-bit magic div
        unsigned q    = g - rowg * CPR;          // chunk within row
        unsigned row  = rowg % D_MODEL;          // diag position in row

        float xv = __ldg(x + rowg);              // L1/L2-hot (x = 5.8 MB)

        unsigned c0 = q * 4u;
        float4 v;
        v.x = (c0      == row) ? xv : 0.f;
        v.y = (c0 + 1u == row) ? xv : 0.f;
        v.z = (c0 + 2u == row) ? xv : 0.f;
        v.w = (c0 + 3u == row) ? xv : 0.f;

        __stcs(out + g, v);                      // sequential streaming store
    }
}

extern "C" void kernel_launch(void* const* d_in, const int* in_sizes, int n_in,
                              void* d_out, int out_size) {
    const float* x = (const float*)d_in[0];
    float4* out = (float4*)d_out;

    unsigned n4   = (unsigned)(out_size / 4);    // 63,438,848 float4 chunks
    unsigned span = (n4 + BLOCKS - 1u) / BLOCKS; // 53,581 chunks per block

    diag_embed_kernel<<<BLOCKS, THREADS>>>(x, out, n4, span);
}